// round 15
// baseline (speedup 1.0000x reference)
#include <cuda_runtime.h>
#include <cuda_bf16.h>
#include <cstdint>

#define NN 1024
#define LL 64

// scratch (allocation-free rule: device globals)
__device__ __align__(16) float g_preib[NN * LL];        // pre_i + be1
__device__ __align__(16) float g_prejT[32 * NN * 2];    // prej transposed: [(k>>1)][j][k&1]
__device__ float g_Vp[NN * 4];                          // per-quadrant V partials
__device__ __align__(16) float g_newH[NN * LL];
__device__ float g_part[128 * LL];
__device__ __align__(16) __nv_bfloat16 g_Bsw[LL * LL];  // We2^T bf16, SW128-swizzled

// HW tanh f32: 1 MUFU op. NOTE (R12): tanh argument must stay f32 —
// bf16x2-argument variant measured rel_err 2.2e-3 (> 1e-3 gate).
__device__ __forceinline__ float htanh(float x) {
    float y;
    asm("tanh.approx.f32 %0, %1;" : "=f"(y) : "f"(x));
    return y;
}

__device__ __forceinline__ uint32_t smem_u32(const void* p) {
    uint32_t a;
    asm("{ .reg .u64 t; cvta.to.shared.u64 t, %1; cvt.u32.u64 %0, t; }" : "=r"(a) : "l"(p));
    return a;
}
__device__ __forceinline__ void ldsm4(uint32_t* r, uint32_t addr) {
    asm volatile("ldmatrix.sync.aligned.m8n8.x4.shared.b16 {%0,%1,%2,%3}, [%4];"
                 : "=r"(r[0]), "=r"(r[1]), "=r"(r[2]), "=r"(r[3]) : "r"(addr));
}
__device__ __forceinline__ void mma16816(float* c, const uint32_t* a, const uint32_t* b) {
    asm volatile(
        "mma.sync.aligned.m16n8k16.row.col.f32.bf16.bf16.f32 "
        "{%0,%1,%2,%3},{%4,%5,%6,%7},{%8,%9},{%0,%1,%2,%3};"
        : "+f"(c[0]), "+f"(c[1]), "+f"(c[2]), "+f"(c[3])
        : "r"(a[0]), "r"(a[1]), "r"(a[2]), "r"(a[3]), "r"(b[0]), "r"(b[1]));
}
__device__ __forceinline__ uint32_t pkbf2(float a, float b) {
    __nv_bfloat162 h = __floats2bfloat162_rn(a, b);
    return *reinterpret_cast<uint32_t*>(&h);
}

// dynamic smem layout (offsets from 1024-aligned base)
#define OFF_B      0u          // 8KB (B bf16, [n][k] swizzled)
#define OFF_D2     8192u       // 2KB (d2 for 256 j's vs i0 and i1)
#define OFF_PWZ    10240u      // 1KB: per k-pair p: {pi0[2p],pi0[2p+1],pi1[2p],pi1[2p+1],w1z[2p],w1z[2p+1],pad,pad}
#define OFF_BE2    11264u      // 256B
#define DYN_BYTES  (11520u + 1024u)

// ---------------------------------------------------------------------------
// Kernel 0: blocks 0..NN-1: preib = H@We1[:L]+be1 ; prejT = (H@We1[L:2L])^T
//           block NN: build swizzled bf16 B = We2^T
// ---------------------------------------------------------------------------
__global__ void prep_kernel(const int* __restrict__ cats,
                            const float* __restrict__ LM,
                            const float* __restrict__ We1,
                            const float* __restrict__ be1,
                            const float* __restrict__ We2) {
    int n = blockIdx.x, l = threadIdx.x;
    if (n == NN) {  // buildB
        for (int idx = l; idx < LL * LL; idx += LL) {
            int nn = idx & 63, k = idx >> 6;
            float f = We2[k * LL + nn];
            uint32_t o = (uint32_t)(nn * 128 + 2 * k);
            o = o ^ ((o >> 3) & 0x70);
            *(__nv_bfloat16*)((char*)g_Bsw + o) = __float2bfloat16(f);
        }
        return;
    }
    __shared__ float Hs[LL];
    Hs[l] = LM[cats[n] * LL + l];
    __syncthreads();
    float ai = be1[l], aj = 0.0f;
#pragma unroll
    for (int k = 0; k < LL; k++) {
        float h = Hs[k];
        ai = fmaf(h, We1[k * LL + l], ai);
        aj = fmaf(h, We1[(LL + k) * LL + l], aj);
    }
    g_preib[n * LL + l] = ai;
    g_prejT[(l >> 1) * (NN * 2) + n * 2 + (l & 1)] = aj;
}

// ---------------------------------------------------------------------------
// Kernel 1: pair kernel, 2048 blocks, TWO atoms per block.
// block: i0 = bid>>2, i1 = i0+512, quad = bid&3; j in [quad*256, +256).
// The 16 prej LDG.64 per warp-tile are shared between both atoms (halves the
// dominant 256MB L2 prej traffic) and per-block setup amortizes over 2 atoms.
// A fragments built directly in mma lane layout for both i's; B in registers.
// ---------------------------------------------------------------------------
__global__ __launch_bounds__(256, 2)
void pair_kernel(const float* __restrict__ coords,
                 const float* __restrict__ We1,
                 const float* __restrict__ be2) {
    extern __shared__ __align__(16) char dyn_raw[];
    char* base = (char*)((((uintptr_t)dyn_raw) + 1023) & ~(uintptr_t)1023);
    const uint32_t sb = smem_u32(base);

    __shared__ float s_red0[8], s_red1[8];

    float* s_d2  = (float*)(base + OFF_D2);    // [0..255]=vs i0, [256..511]=vs i1
    float* s_pwz = (float*)(base + OFF_PWZ);
    float* s_be2 = (float*)(base + OFF_BE2);

    const int i0   = blockIdx.x >> 2;
    const int i1   = i0 + 512;
    const int quad = blockIdx.x & 3;
    const int jq   = quad * 256;
    const int t = threadIdx.x;
    const int w = t >> 5, lane = t & 31;

    // ---- stage pre-swizzled B (8KB copy), d2 for both i, vectors ----
    {
        const uint4* src = (const uint4*)g_Bsw;
        uint4* dst = (uint4*)(base + OFF_B);
        dst[t]       = src[t];
        dst[t + 256] = src[t + 256];
    }
    {
        int j = jq + t;
        float cx = coords[3 * j], cy = coords[3 * j + 1], cz = coords[3 * j + 2];
        float dx0 = coords[3 * i0] - cx;
        float dy0 = coords[3 * i0 + 1] - cy;
        float dz0 = coords[3 * i0 + 2] - cz;
        s_d2[t] = dx0 * dx0 + dy0 * dy0 + dz0 * dz0;
        float dx1 = coords[3 * i1] - cx;
        float dy1 = coords[3 * i1 + 1] - cy;
        float dz1 = coords[3 * i1 + 2] - cz;
        s_d2[256 + t] = dx1 * dx1 + dy1 * dy1 + dz1 * dz1;
    }
    if (t < 32) {   // per k-pair record (32B): preib_i0 x2, preib_i1 x2, w1z x2
        int p = t;
        s_pwz[p * 8 + 0] = g_preib[i0 * LL + 2 * p];
        s_pwz[p * 8 + 1] = g_preib[i0 * LL + 2 * p + 1];
        s_pwz[p * 8 + 2] = g_preib[i1 * LL + 2 * p];
        s_pwz[p * 8 + 3] = g_preib[i1 * LL + 2 * p + 1];
        s_pwz[p * 8 + 4] = We1[2 * LL * LL + 2 * p];
        s_pwz[p * 8 + 5] = We1[2 * LL * LL + 2 * p + 1];
    }
    if (t >= 64 && t < 128) s_be2[t - 64] = be2[t - 64];
    __syncthreads();

    // ldmatrix B lane mapping (x4 covers n-pair x k-halves)
    const int brow = lane & 7;
    const int bg   = lane >> 3;
    const uint32_t bns  = (uint32_t)(bg >> 1) * 1024u;
    const uint32_t bks  = (uint32_t)(bg & 1) * 16u;
    const uint32_t xorB = (uint32_t)(brow << 4);
    const uint32_t bB   = sb + OFF_B + bns + (uint32_t)brow * 128u;

    // ---- hoist ALL B fragments into registers (once per block) ----
    uint32_t breg[4][4][4];
#pragma unroll
    for (int ntp = 0; ntp < 4; ntp++)
#pragma unroll
        for (int kk = 0; kk < 4; kk++) {
            uint32_t col = ((uint32_t)(kk * 32) + bks) ^ xorB;
            ldsm4(breg[ntp][kk], bB + (uint32_t)(ntp * 2048) + col);
        }

    // fragment lane mapping
    const int rquad = lane >> 2;           // row within tile (and +8)
    const int cpair = (lane & 3) * 2;      // col pair base
    const int cb = cpair;                  // epilogue be2 col base
    const int pb = cpair >> 1;             // k-pair index base

    float vp0 = 0.0f, vp1 = 0.0f;

#pragma unroll
    for (int tt = 0; tt < 2; tt++) {
        const int tile = w + tt * 8;            // 0..15 within quadrant
        const int jloc = tile * 16;
        const int jbase = jq + jloc;

        // ---------------- phase 1: A fragments for BOTH atoms ----------
        const float d2a0 = s_d2[jloc + rquad];
        const float d2b0 = s_d2[jloc + rquad + 8];
        const float d2a1 = s_d2[256 + jloc + rquad];
        const float d2b1 = s_d2[256 + jloc + rquad + 8];
        const float* pT = g_prejT + (jbase + rquad) * 2;

        uint32_t ahi0[4][4], ahi1[4][4];
#pragma unroll
        for (int kk = 0; kk < 4; kk++) {
            const int p = pb + 8 * kk;       // k-pair for cols c, c+1
            float4 q  = *(const float4*)&s_pwz[p * 8];        // pi0 x2, pi1 x2
            float2 qw = *(const float2*)&s_pwz[p * 8 + 4];    // w1z x2
            float4 r  = *(const float4*)&s_pwz[(p + 4) * 8];  // cols c+8, c+9
            float2 rw = *(const float2*)&s_pwz[(p + 4) * 8 + 4];
            // shared prej loads (one line each, i-independent)
            float2 pA0 = *(const float2*)(pT + p * (NN * 2));
            float2 pB0 = *(const float2*)(pT + p * (NN * 2) + 16);
            float2 pA1 = *(const float2*)(pT + (p + 4) * (NN * 2));
            float2 pB1 = *(const float2*)(pT + (p + 4) * (NN * 2) + 16);
            ahi0[kk][0] = pkbf2(htanh(fmaf(d2a0, qw.x, q.x + pA0.x)),
                                htanh(fmaf(d2a0, qw.y, q.y + pA0.y)));
            ahi1[kk][0] = pkbf2(htanh(fmaf(d2a1, qw.x, q.z + pA0.x)),
                                htanh(fmaf(d2a1, qw.y, q.w + pA0.y)));
            ahi0[kk][1] = pkbf2(htanh(fmaf(d2b0, qw.x, q.x + pB0.x)),
                                htanh(fmaf(d2b0, qw.y, q.y + pB0.y)));
            ahi1[kk][1] = pkbf2(htanh(fmaf(d2b1, qw.x, q.z + pB0.x)),
                                htanh(fmaf(d2b1, qw.y, q.w + pB0.y)));
            ahi0[kk][2] = pkbf2(htanh(fmaf(d2a0, rw.x, r.x + pA1.x)),
                                htanh(fmaf(d2a0, rw.y, r.y + pA1.y)));
            ahi1[kk][2] = pkbf2(htanh(fmaf(d2a1, rw.x, r.z + pA1.x)),
                                htanh(fmaf(d2a1, rw.y, r.w + pA1.y)));
            ahi0[kk][3] = pkbf2(htanh(fmaf(d2b0, rw.x, r.x + pB1.x)),
                                htanh(fmaf(d2b0, rw.y, r.y + pB1.y)));
            ahi1[kk][3] = pkbf2(htanh(fmaf(d2b1, rw.x, r.z + pB1.x)),
                                htanh(fmaf(d2b1, rw.y, r.w + pB1.y)));
        }

        // ---------------- phase 2: MMAs + epilogue, atom i0 then i1 ----
        const bool mt0 = (jbase <= i0) && (i0 < jbase + 16);
        const bool mt1 = (jbase <= i1) && (i1 < jbase + 16);
        const int ri0 = i0 - jbase, ri1 = i1 - jbase;
#pragma unroll
        for (int ntp = 0; ntp < 4; ntp++) {
            const int n0 = 2 * ntp, nx = n0 + 1;
            float b00 = s_be2[n0 * 8 + cb], b01 = s_be2[n0 * 8 + cb + 1];
            float b10 = s_be2[nx * 8 + cb], b11 = s_be2[nx * 8 + cb + 1];
            {
                float c0[4] = {b00, b01, b00, b01};
                float c1[4] = {b10, b11, b10, b11};
#pragma unroll
                for (int kk = 0; kk < 4; kk++) {
                    mma16816(c0, ahi0[kk], breg[ntp][kk]);
                    mma16816(c1, ahi0[kk], breg[ntp][kk] + 2);
                }
                float a0 = htanh(c0[0]) + htanh(c0[1]) + htanh(c1[0]) + htanh(c1[1]);
                float a1 = htanh(c0[2]) + htanh(c0[3]) + htanh(c1[2]) + htanh(c1[3]);
                if (!(mt0 && rquad == ri0))     vp0 += a0;
                if (!(mt0 && rquad + 8 == ri0)) vp0 += a1;
            }
            {
                float c0[4] = {b00, b01, b00, b01};
                float c1[4] = {b10, b11, b10, b11};
#pragma unroll
                for (int kk = 0; kk < 4; kk++) {
                    mma16816(c0, ahi1[kk], breg[ntp][kk]);
                    mma16816(c1, ahi1[kk], breg[ntp][kk] + 2);
                }
                float a0 = htanh(c0[0]) + htanh(c0[1]) + htanh(c1[0]) + htanh(c1[1]);
                float a1 = htanh(c0[2]) + htanh(c0[3]) + htanh(c1[2]) + htanh(c1[3]);
                if (!(mt1 && rquad == ri1))     vp1 += a0;
                if (!(mt1 && rquad + 8 == ri1)) vp1 += a1;
            }
        }
    }

    // reduce over warp + block -> Vp
#pragma unroll
    for (int o = 16; o > 0; o >>= 1) {
        vp0 += __shfl_down_sync(0xffffffffu, vp0, o);
        vp1 += __shfl_down_sync(0xffffffffu, vp1, o);
    }
    if (lane == 0) { s_red0[w] = vp0; s_red1[w] = vp1; }
    __syncthreads();
    if (t == 0) {
        float v0 = 0.f, v1 = 0.f;
#pragma unroll
        for (int q = 0; q < 8; q++) { v0 += s_red0[q]; v1 += s_red1[q]; }
        g_Vp[i0 * 4 + quad] = v0;
        g_Vp[i1 * 4 + quad] = v1;
    }
}

// ---------------------------------------------------------------------------
// Kernel 2: head. V = sum of 4 quadrant partials.
// ---------------------------------------------------------------------------
__global__ void head_kernel(const int* __restrict__ cats,
                            const float* __restrict__ LM,
                            const float* __restrict__ Wh1,
                            const float* __restrict__ bh1,
                            const float* __restrict__ Wh2,
                            const float* __restrict__ bh2) {
    __shared__ float Hs[LL];
    __shared__ float hhs[LL];
    int n = blockIdx.x, l = threadIdx.x;
    Hs[l] = LM[cats[n] * LL + l];
    __syncthreads();
    float V = (g_Vp[n * 4 + 0] + g_Vp[n * 4 + 1]) + (g_Vp[n * 4 + 2] + g_Vp[n * 4 + 3]);
    float acc = fmaf(V, Wh1[LL * LL + l], bh1[l]);
#pragma unroll
    for (int k = 0; k < LL; k++)
        acc = fmaf(Hs[k], Wh1[k * LL + l], acc);
    hhs[l] = tanhf(acc);
    __syncthreads();
    float acc2 = bh2[l];
#pragma unroll
    for (int k = 0; k < LL; k++)
        acc2 = fmaf(hhs[k], Wh2[k * LL + l], acc2);
    g_newH[n * LL + l] = tanhf(acc2);
}

// ---------------------------------------------------------------------------
// Kernel 3/4: final reduction (128-block partials + tiny dot)
// ---------------------------------------------------------------------------
__global__ void final1_kernel() {
    __shared__ float s[256];
    int b = blockIdx.x, t = threadIdx.x;
    int l = t & 63, r = t >> 6;
    float acc = 0.f;
#pragma unroll
    for (int m = 0; m < 2; m++) {
        int n = b * 8 + r * 2 + m;
        acc += g_newH[n * LL + l];
    }
    s[t] = acc;
    __syncthreads();
    if (t < 64)
        g_part[b * LL + t] = s[t] + s[t + 64] + s[t + 128] + s[t + 192];
}

__global__ void final2_kernel(const float* __restrict__ Wo,
                              const float* __restrict__ bo,
                              float* __restrict__ out) {
    __shared__ float s_w[2];
    int t = threadIdx.x;          // 64 threads
    float h = 0.f;
#pragma unroll
    for (int q = 0; q < 128; q++)
        h += g_part[q * LL + t];
    float v = h * Wo[t];
#pragma unroll
    for (int o = 16; o > 0; o >>= 1)
        v += __shfl_down_sync(0xffffffffu, v, o);
    if ((t & 31) == 0) s_w[t >> 5] = v;
    __syncthreads();
    if (t == 0) out[0] = s_w[0] + s_w[1] + bo[0];
}

// ---------------------------------------------------------------------------
extern "C" void kernel_launch(void* const* d_in, const int* in_sizes, int n_in,
                              void* d_out, int out_size) {
    (void)in_sizes; (void)n_in; (void)out_size;
    const int*   cats   = (const int*)  d_in[0];
    const float* coords = (const float*)d_in[1];
    const float* LM     = (const float*)d_in[2];
    const float* We1    = (const float*)d_in[3];
    const float* be1    = (const float*)d_in[4];
    const float* We2    = (const float*)d_in[5];
    const float* be2    = (const float*)d_in[6];
    const float* Wh1    = (const float*)d_in[7];
    const float* bh1    = (const float*)d_in[8];
    const float* Wh2    = (const float*)d_in[9];
    const float* bh2    = (const float*)d_in[10];
    const float* Wo     = (const float*)d_in[11];
    const float* bo     = (const float*)d_in[12];

    cudaFuncSetAttribute(pair_kernel,
                         cudaFuncAttributeMaxDynamicSharedMemorySize, DYN_BYTES);

    prep_kernel  <<<NN + 1, LL>>>(cats, LM, We1, be1, We2);
    pair_kernel  <<<2048, 256, DYN_BYTES>>>(coords, We1, be2);
    head_kernel  <<<NN, LL>>>(cats, LM, Wh1, bh1, Wh2, bh2);
    final1_kernel<<<128, 256>>>();
    final2_kernel<<<1, 64>>>(Wo, bo, (float*)d_out);
}